// round 1
// baseline (speedup 1.0000x reference)
#include <cuda_runtime.h>

// DiffPool: B=8, N=2048, F=C=K=128.
// out layout (float32): X_pooled[8,128,128] | A_pooled[8,128,128] | S[8,2048,128] | LP_loss | entr_loss

#define BB 8
#define NN 2048
#define ROWS (BB*NN)          // 16384
#define CAP 512               // neighbor-list capacity (mean nnz ~200, sigma ~13)
#define OUT_AP 131072
#define OUT_S  262144
#define OUT_LP 2359296
#define OUT_ENT 2359297

// ---- scratch (static __device__: no runtime allocation) ----
__device__ float g_Y[(size_t)ROWS*256];              // d-scaled [XW_emb | XW_pool]
__device__ float g_Z[(size_t)ROWS*128];              // embedding GNN output
__device__ float g_T[(size_t)ROWS*128];              // T = A @ S
__device__ float g_d[ROWS];
__device__ int   g_nnz[ROWS];
__device__ unsigned short g_nbr[(size_t)ROWS*CAP];
__device__ float g_entrRow[ROWS];
__device__ float g_part[(size_t)3*8*16*16384];       // split-K partials for S^T products
__device__ float g_G[8*128*128];                     // G = S^T S

// =====================================================================
// K1: per-row scan of A: nnz count, neighbor index list, d = rsqrt(sum+1)
// =====================================================================
__global__ void k1_scan(const float* __restrict__ A) {
    int row = blockIdx.x;
    const float* ar = A + (size_t)row * NN;
    int t = threadIdx.x;                     // 256 threads
    unsigned short loc[8];
    int cnt = 0;
    #pragma unroll
    for (int i = 0; i < 8; i++) {
        int c = t + (i << 8);
        if (ar[c] != 0.0f) loc[cnt++] = (unsigned short)c;
    }
    int lane = t & 31, w = t >> 5;
    int incl = cnt;
    #pragma unroll
    for (int o = 1; o < 32; o <<= 1) {
        int v = __shfl_up_sync(0xffffffffu, incl, o);
        if (lane >= o) incl += v;
    }
    __shared__ int wtot[8], woff[8];
    if (lane == 31) wtot[w] = incl;
    __syncthreads();
    if (t == 0) {
        int s = 0;
        for (int i = 0; i < 8; i++) { woff[i] = s; s += wtot[i]; }
        g_nnz[row] = s;
        g_d[row] = rsqrtf((float)s + 1.0f);
    }
    __syncthreads();
    int off = woff[w] + (incl - cnt);
    unsigned short* dst = g_nbr + (size_t)row * CAP;
    for (int i = 0; i < cnt; i++) {
        int o = off + i;
        if (o < CAP) dst[o] = loc[i];
    }
}

// =====================================================================
// K2: Y[row, 0:256] = d[row] * (X[row,:] @ [W_emb | W_pool])
// block: 32 rows x 256 cols, 256 threads, 4x8 register tile
// =====================================================================
__global__ void k2_xw(const float* __restrict__ X, const float* __restrict__ We,
                      const float* __restrict__ Wp) {
    __shared__ float shW[32][256];
    __shared__ float shX[32][32];
    int t = threadIdx.x;
    int tx = t & 31, ty = t >> 5;
    int row0 = blockIdx.x * 32;
    float acc[4][8];
    #pragma unroll
    for (int i = 0; i < 4; i++)
        #pragma unroll
        for (int j = 0; j < 8; j++) acc[i][j] = 0.f;

    for (int kb = 0; kb < 4; kb++) {
        __syncthreads();
        #pragma unroll
        for (int r = 0; r < 32; r++) {
            int k = kb * 32 + r;
            shW[r][t] = (t < 128) ? We[k * 128 + t] : Wp[k * 128 + (t - 128)];
        }
        #pragma unroll
        for (int r = 0; r < 4; r++) {
            int li = t + (r << 8);
            int rr = li >> 5, kk = li & 31;
            shX[rr][kk] = X[(size_t)(row0 + rr) * 128 + kb * 32 + kk];
        }
        __syncthreads();
        #pragma unroll
        for (int kk = 0; kk < 32; kk++) {
            float x0 = shX[ty][kk], x1 = shX[ty + 8][kk];
            float x2 = shX[ty + 16][kk], x3 = shX[ty + 24][kk];
            float wv[8];
            #pragma unroll
            for (int j = 0; j < 8; j++) wv[j] = shW[kk][tx * 8 + j];
            #pragma unroll
            for (int j = 0; j < 8; j++) {
                acc[0][j] += x0 * wv[j];
                acc[1][j] += x1 * wv[j];
                acc[2][j] += x2 * wv[j];
                acc[3][j] += x3 * wv[j];
            }
        }
    }
    #pragma unroll
    for (int r = 0; r < 4; r++) {
        int row = row0 + ty + r * 8;
        float dv = g_d[row];
        #pragma unroll
        for (int j = 0; j < 8; j++)
            g_Y[(size_t)row * 256 + tx * 8 + j] = dv * acc[r][j];
    }
}

// =====================================================================
// K3: sparse propagate + softmax + entropy.
// acc[c] = Y[n,c] + sum_{m in nbr(n)} Y[m,c];  Z = d*acc[0:128];
// S = softmax(d*acc[128:256]); entropy per row.
// one block per row, 256 threads (one col each)
// =====================================================================
__global__ void k3_prop(float* __restrict__ out) {
    int row = blockIdx.x;
    int b = row >> 11;
    int t = threadIdx.x;
    float d = g_d[row];
    int nnz = g_nnz[row]; if (nnz > CAP) nnz = CAP;
    const float* Yb = g_Y + (size_t)(b << 11) * 256;
    const unsigned short* nb = g_nbr + (size_t)row * CAP;
    float acc = g_Y[(size_t)row * 256 + t];      // identity (+I) term

    __shared__ unsigned short sidx[256];
    for (int base = 0; base < nnz; base += 256) {
        int c = nnz - base; if (c > 256) c = 256;
        __syncthreads();
        if (t < c) sidx[t] = nb[base + t];
        __syncthreads();
        int j = 0;
        for (; j + 4 <= c; j += 4) {
            float v0 = Yb[(size_t)sidx[j]     * 256 + t];
            float v1 = Yb[(size_t)sidx[j + 1] * 256 + t];
            float v2 = Yb[(size_t)sidx[j + 2] * 256 + t];
            float v3 = Yb[(size_t)sidx[j + 3] * 256 + t];
            acc += (v0 + v1) + (v2 + v3);
        }
        for (; j < c; j++) acc += Yb[(size_t)sidx[j] * 256 + t];
    }
    __syncthreads();

    if (t < 128) g_Z[(size_t)row * 128 + t] = d * acc;

    float lg = d * acc;                          // logit (valid for t>=128)
    __shared__ float red[128];
    if (t >= 128) red[t - 128] = lg;
    __syncthreads();
    for (int s2 = 64; s2 > 0; s2 >>= 1) {
        if (t < s2) red[t] = fmaxf(red[t], red[t + s2]);
        __syncthreads();
    }
    float mx = red[0];
    __syncthreads();
    float e = (t >= 128) ? expf(lg - mx) : 0.f;
    if (t >= 128) red[t - 128] = e;
    __syncthreads();
    for (int s2 = 64; s2 > 0; s2 >>= 1) {
        if (t < s2) red[t] += red[t + s2];
        __syncthreads();
    }
    float sum = red[0];
    __syncthreads();
    float s = e / sum;
    if (t >= 128) {
        out[OUT_S + (size_t)row * 128 + (t - 128)] = s;
        red[t - 128] = -s * logf(s + 1e-7f);
    }
    __syncthreads();
    for (int s2 = 64; s2 > 0; s2 >>= 1) {
        if (t < s2) red[t] += red[t + s2];
        __syncthreads();
    }
    if (t == 0) g_entrRow[row] = red[0];
}

// =====================================================================
// K4: T = A @ S via neighbor gather. one block per row, 128 threads
// =====================================================================
__global__ void k4_AS(const float* __restrict__ out) {
    int row = blockIdx.x;
    int b = row >> 11;
    int t = threadIdx.x;
    int nnz = g_nnz[row]; if (nnz > CAP) nnz = CAP;
    const float* Sb = out + OUT_S + (size_t)(b << 11) * 128;
    const unsigned short* nb = g_nbr + (size_t)row * CAP;
    float acc = 0.f;

    __shared__ unsigned short sidx[128];
    for (int base = 0; base < nnz; base += 128) {
        int c = nnz - base; if (c > 128) c = 128;
        __syncthreads();
        if (t < c) sidx[t] = nb[base + t];
        __syncthreads();
        int j = 0;
        for (; j + 4 <= c; j += 4) {
            float v0 = Sb[(size_t)sidx[j]     * 128 + t];
            float v1 = Sb[(size_t)sidx[j + 1] * 128 + t];
            float v2 = Sb[(size_t)sidx[j + 2] * 128 + t];
            float v3 = Sb[(size_t)sidx[j + 3] * 128 + t];
            acc += (v0 + v1) + (v2 + v3);
        }
        for (; j < c; j++) acc += Sb[(size_t)sidx[j] * 128 + t];
    }
    g_T[(size_t)row * 128 + t] = acc;
}

// =====================================================================
// K5: split-K outer-product GEMMs: for p in {0,1,2}: S^T @ {Z, T, S}
// grid (chunk=16, b=8, p=3); block 256 threads, 8x8 register tile
// =====================================================================
__global__ void k5_outer(const float* __restrict__ out) {
    int ch = blockIdx.x, b = blockIdx.y, p = blockIdx.z;
    const float* Sb = out + OUT_S + (size_t)b * 262144;
    const float* L = Sb;
    const float* R = (p == 0) ? (g_Z + (size_t)b * 262144)
                   : (p == 1) ? (g_T + (size_t)b * 262144)
                   : Sb;
    int t = threadIdx.x;
    int tx = t & 15, ty = t >> 4;
    float acc[8][8];
    #pragma unroll
    for (int i = 0; i < 8; i++)
        #pragma unroll
        for (int j = 0; j < 8; j++) acc[i][j] = 0.f;

    __shared__ float shL[8][128], shR[8][128];
    int n0 = ch * 128;
    for (int nn = 0; nn < 128; nn += 8) {
        __syncthreads();
        #pragma unroll
        for (int r = 0; r < 4; r++) {
            int li = t + (r << 8);
            int rr = li >> 7, cc = li & 127;
            shL[rr][cc] = L[(size_t)(n0 + nn + rr) * 128 + cc];
            shR[rr][cc] = R[(size_t)(n0 + nn + rr) * 128 + cc];
        }
        __syncthreads();
        #pragma unroll
        for (int q = 0; q < 8; q++) {
            float lv[8], rv[8];
            #pragma unroll
            for (int i = 0; i < 8; i++) lv[i] = shL[q][ty * 8 + i];
            #pragma unroll
            for (int j = 0; j < 8; j++) rv[j] = shR[q][tx * 8 + j];
            #pragma unroll
            for (int i = 0; i < 8; i++)
                #pragma unroll
                for (int j = 0; j < 8; j++) acc[i][j] += lv[i] * rv[j];
        }
    }
    float* dst = g_part + (size_t)((p * 8 + b) * 16 + ch) * 16384;
    #pragma unroll
    for (int i = 0; i < 8; i++)
        #pragma unroll
        for (int j = 0; j < 8; j++)
            dst[(ty * 8 + i) * 128 + tx * 8 + j] = acc[i][j];
}

// =====================================================================
// K5b: reduce split-K partials -> X_pooled, A_pooled (out), G (scratch)
// =====================================================================
__global__ void k5b_reduce(float* __restrict__ out) {
    int idx = blockIdx.x * blockDim.x + threadIdx.x;
    if (idx >= 3 * 8 * 16384) return;
    int p = idx / 131072;
    int rem = idx - p * 131072;
    int b = rem >> 14;
    int kc = rem & 16383;
    const float* src = g_part + (size_t)((p * 8 + b) * 16) * 16384 + kc;
    float s = 0.f;
    #pragma unroll
    for (int ch = 0; ch < 16; ch++) s += src[(size_t)ch * 16384];
    if (p == 0)      out[(size_t)b * 16384 + kc] = s;
    else if (p == 1) out[OUT_AP + (size_t)b * 16384 + kc] = s;
    else             g_G[b * 16384 + kc] = s;
}

// =====================================================================
// K6: finalize losses.
// LP_b^2 = sumA_b - 2*trace(A_pooled_b) + ||G_b||_F^2  (A binary => sumA^2 = sumA)
// =====================================================================
__global__ void k6_final(float* __restrict__ out) {
    int t = threadIdx.x;                       // 256
    __shared__ float red[256];

    float lo = 0.f;
    for (int i = t; i < ROWS; i += 256) lo += g_entrRow[i];
    red[t] = lo; __syncthreads();
    for (int s2 = 128; s2 > 0; s2 >>= 1) {
        if (t < s2) red[t] += red[t + s2];
        __syncthreads();
    }
    float entr = red[0] / (float)ROWS;
    __syncthreads();

    float lpsum = 0.f;
    for (int b = 0; b < 8; b++) {
        float la = 0.f;
        for (int i = t; i < NN; i += 256) la += (float)g_nnz[b * NN + i];
        red[t] = la; __syncthreads();
        for (int s2 = 128; s2 > 0; s2 >>= 1) { if (t < s2) red[t] += red[t + s2]; __syncthreads(); }
        float sumA = red[0]; __syncthreads();

        float ltr = (t < 128) ? out[OUT_AP + (size_t)b * 16384 + t * 129] : 0.f;
        red[t] = ltr; __syncthreads();
        for (int s2 = 128; s2 > 0; s2 >>= 1) { if (t < s2) red[t] += red[t + s2]; __syncthreads(); }
        float tr = red[0]; __syncthreads();

        float lg = 0.f;
        for (int i = t; i < 16384; i += 256) { float v = g_G[b * 16384 + i]; lg += v * v; }
        red[t] = lg; __syncthreads();
        for (int s2 = 128; s2 > 0; s2 >>= 1) { if (t < s2) red[t] += red[t + s2]; __syncthreads(); }
        float gg = red[0]; __syncthreads();

        lpsum += sqrtf(fmaxf(sumA - 2.f * tr + gg, 0.f));
    }
    if (t == 0) {
        out[OUT_LP] = lpsum / 8.0f;
        out[OUT_ENT] = entr;
    }
}

// =====================================================================
extern "C" void kernel_launch(void* const* d_in, const int* in_sizes, int n_in,
                              void* d_out, int out_size) {
    const float* X  = (const float*)d_in[0];
    const float* A  = (const float*)d_in[1];
    const float* We = (const float*)d_in[2];
    const float* Wp = (const float*)d_in[3];
    float* out = (float*)d_out;

    k1_scan<<<ROWS, 256>>>(A);
    k2_xw<<<ROWS / 32, 256>>>(X, We, Wp);
    k3_prop<<<ROWS, 256>>>(out);
    k4_AS<<<ROWS, 128>>>(out);
    dim3 g5(16, 8, 3);
    k5_outer<<<g5, 256>>>(out);
    k5b_reduce<<<(3 * 8 * 16384 + 255) / 256, 256>>>(out);
    k6_final<<<1, 256>>>(out);
}

// round 2
// speedup vs baseline: 1.3683x; 1.3683x over previous
#include <cuda_runtime.h>

// DiffPool: B=8, N=2048, F=C=K=128.
// out layout (float32): X_pooled[8,128,128] | A_pooled[8,128,128] | S[8,2048,128] | LP_loss | entr_loss

#define BB 8
#define NN 2048
#define ROWS (BB*NN)          // 16384
#define CAP 512               // neighbor-list capacity (mean nnz ~200)
#define OUT_AP 131072
#define OUT_S  262144
#define OUT_LP 2359296
#define OUT_ENT 2359297

// ---- scratch (static __device__: no runtime allocation) ----
__device__ float4 g_Y4[(size_t)ROWS*64];             // d-scaled [XW_emb | XW_pool], 256 f32/row
__device__ float4 g_Z4[(size_t)ROWS*32];             // embedding GNN output, 128 f32/row
__device__ float4 g_T4[(size_t)ROWS*32];             // T = A @ S
__device__ float g_d[ROWS];
__device__ int   g_nnz[ROWS];
__device__ unsigned short g_nbr[(size_t)ROWS*CAP];
__device__ float g_entrRow[ROWS];
__device__ float g_part[(size_t)3*8*16*16384];       // split-K partials for S^T products
__device__ float g_G[8*128*128];                     // G = S^T S

// =====================================================================
// K1: per-row scan of A (float4 loads): nnz, neighbor list, d = rsqrt(sum+1)
// =====================================================================
__global__ void k1_scan(const float* __restrict__ A) {
    int row = blockIdx.x;
    const float4* ar = reinterpret_cast<const float4*>(A + (size_t)row * NN);
    int t = threadIdx.x;                     // 256 threads
    unsigned short loc[8];
    int cnt = 0;
    #pragma unroll
    for (int i = 0; i < 2; i++) {
        int cg = t + (i << 8);               // float4 group 0..511
        float4 v = ar[cg];
        int c0 = cg << 2;
        if (v.x != 0.0f) loc[cnt++] = (unsigned short)(c0);
        if (v.y != 0.0f) loc[cnt++] = (unsigned short)(c0 + 1);
        if (v.z != 0.0f) loc[cnt++] = (unsigned short)(c0 + 2);
        if (v.w != 0.0f) loc[cnt++] = (unsigned short)(c0 + 3);
    }
    int lane = t & 31, w = t >> 5;
    int incl = cnt;
    #pragma unroll
    for (int o = 1; o < 32; o <<= 1) {
        int v = __shfl_up_sync(0xffffffffu, incl, o);
        if (lane >= o) incl += v;
    }
    __shared__ int wtot[8], woff[8];
    if (lane == 31) wtot[w] = incl;
    __syncthreads();
    if (t == 0) {
        int s = 0;
        for (int i = 0; i < 8; i++) { woff[i] = s; s += wtot[i]; }
        g_nnz[row] = s;
        g_d[row] = rsqrtf((float)s + 1.0f);
    }
    __syncthreads();
    int off = woff[w] + (incl - cnt);
    unsigned short* dst = g_nbr + (size_t)row * CAP;
    for (int i = 0; i < cnt; i++) {
        int o = off + i;
        if (o < CAP) dst[o] = loc[i];
    }
}

// =====================================================================
// K2: Y[row, 0:256] = d[row] * (X[row,:] @ [W_emb | W_pool])
// =====================================================================
__global__ void k2_xw(const float* __restrict__ X, const float* __restrict__ We,
                      const float* __restrict__ Wp) {
    __shared__ float shW[32][256];
    __shared__ float shX[32][32];
    int t = threadIdx.x;
    int tx = t & 31, ty = t >> 5;
    int row0 = blockIdx.x * 32;
    float acc[4][8];
    #pragma unroll
    for (int i = 0; i < 4; i++)
        #pragma unroll
        for (int j = 0; j < 8; j++) acc[i][j] = 0.f;

    for (int kb = 0; kb < 4; kb++) {
        __syncthreads();
        #pragma unroll
        for (int r = 0; r < 32; r++) {
            int k = kb * 32 + r;
            shW[r][t] = (t < 128) ? We[k * 128 + t] : Wp[k * 128 + (t - 128)];
        }
        #pragma unroll
        for (int r = 0; r < 4; r++) {
            int li = t + (r << 8);
            int rr = li >> 5, kk = li & 31;
            shX[rr][kk] = X[(size_t)(row0 + rr) * 128 + kb * 32 + kk];
        }
        __syncthreads();
        #pragma unroll
        for (int kk = 0; kk < 32; kk++) {
            float x0 = shX[ty][kk], x1 = shX[ty + 8][kk];
            float x2 = shX[ty + 16][kk], x3 = shX[ty + 24][kk];
            float wv[8];
            #pragma unroll
            for (int j = 0; j < 8; j++) wv[j] = shW[kk][tx * 8 + j];
            #pragma unroll
            for (int j = 0; j < 8; j++) {
                acc[0][j] += x0 * wv[j];
                acc[1][j] += x1 * wv[j];
                acc[2][j] += x2 * wv[j];
                acc[3][j] += x3 * wv[j];
            }
        }
    }
    #pragma unroll
    for (int r = 0; r < 4; r++) {
        int row = row0 + ty + r * 8;
        float dv = g_d[row];
        #pragma unroll
        for (int jj = 0; jj < 2; jj++) {
            float4 v;
            v.x = dv * acc[r][jj * 4 + 0];
            v.y = dv * acc[r][jj * 4 + 1];
            v.z = dv * acc[r][jj * 4 + 2];
            v.w = dv * acc[r][jj * 4 + 3];
            g_Y4[(size_t)row * 64 + tx * 2 + jj] = v;
        }
    }
}

// =====================================================================
// K3: vectorized sparse propagate + warp-shuffle softmax + entropy.
// block 256: tx = float4 col group (0..63), g = neighbor subset (0..3)
// =====================================================================
__global__ void k3_prop(float* __restrict__ out) {
    int row = blockIdx.x;
    int b = row >> 11;
    int t = threadIdx.x;
    int tx = t & 63, g = t >> 6;
    float d = g_d[row];
    int nnz = g_nnz[row]; if (nnz > CAP) nnz = CAP;
    const float4* Yb = g_Y4 + (size_t)(b << 11) * 64;
    const unsigned short* nb = g_nbr + (size_t)row * CAP;

    __shared__ unsigned short sidx[CAP];
    for (int i = t; i < nnz; i += 256) sidx[i] = nb[i];
    __syncthreads();

    float4 acc = make_float4(0.f, 0.f, 0.f, 0.f);
    if (g == 0) acc = g_Y4[(size_t)row * 64 + tx];     // identity (+I) term
    int j = g;
    for (; j + 12 < nnz; j += 16) {
        float4 v0 = Yb[(size_t)sidx[j]      * 64 + tx];
        float4 v1 = Yb[(size_t)sidx[j + 4]  * 64 + tx];
        float4 v2 = Yb[(size_t)sidx[j + 8]  * 64 + tx];
        float4 v3 = Yb[(size_t)sidx[j + 12] * 64 + tx];
        acc.x += (v0.x + v1.x) + (v2.x + v3.x);
        acc.y += (v0.y + v1.y) + (v2.y + v3.y);
        acc.z += (v0.z + v1.z) + (v2.z + v3.z);
        acc.w += (v0.w + v1.w) + (v2.w + v3.w);
    }
    for (; j < nnz; j += 4) {
        float4 v = Yb[(size_t)sidx[j] * 64 + tx];
        acc.x += v.x; acc.y += v.y; acc.z += v.z; acc.w += v.w;
    }

    __shared__ float4 sred[4][64];
    sred[g][tx] = acc;
    __syncthreads();
    if (t < 64) {
        float4 a1 = sred[1][tx], a2 = sred[2][tx], a3 = sred[3][tx];
        acc.x = (acc.x + a1.x) + (a2.x + a3.x);
        acc.y = (acc.y + a1.y) + (a2.y + a3.y);
        acc.z = (acc.z + a1.z) + (a2.z + a3.z);
        acc.w = (acc.w + a1.w) + (a2.w + a3.w);
    }

    if (t < 32) {
        // Z = d * acc  (cols 0:128)
        float4 z; z.x = d * acc.x; z.y = d * acc.y; z.z = d * acc.z; z.w = d * acc.w;
        g_Z4[(size_t)row * 32 + tx] = z;
    } else if (t < 64) {
        // softmax over 128 logits held entirely in warp 1 (32 lanes x float4)
        float4 lg; lg.x = d * acc.x; lg.y = d * acc.y; lg.z = d * acc.z; lg.w = d * acc.w;
        float m = fmaxf(fmaxf(lg.x, lg.y), fmaxf(lg.z, lg.w));
        #pragma unroll
        for (int o = 16; o > 0; o >>= 1) m = fmaxf(m, __shfl_xor_sync(0xffffffffu, m, o));
        float ex = expf(lg.x - m), ey = expf(lg.y - m);
        float ez = expf(lg.z - m), ew = expf(lg.w - m);
        float ssum = (ex + ey) + (ez + ew);
        #pragma unroll
        for (int o = 16; o > 0; o >>= 1) ssum += __shfl_xor_sync(0xffffffffu, ssum, o);
        float inv = 1.f / ssum;
        float4 s4; s4.x = ex * inv; s4.y = ey * inv; s4.z = ez * inv; s4.w = ew * inv;
        reinterpret_cast<float4*>(out + OUT_S)[(size_t)row * 32 + (tx - 32)] = s4;
        float ent = -(s4.x * logf(s4.x + 1e-7f) + s4.y * logf(s4.y + 1e-7f)
                    + s4.z * logf(s4.z + 1e-7f) + s4.w * logf(s4.w + 1e-7f));
        #pragma unroll
        for (int o = 16; o > 0; o >>= 1) ent += __shfl_xor_sync(0xffffffffu, ent, o);
        if ((t & 31) == 0) g_entrRow[row] = ent;
    }
}

// =====================================================================
// K4: T = A @ S, vectorized. block 128: tx = float4 group (0..31), g = subset
// =====================================================================
__global__ void k4_AS(const float* __restrict__ out) {
    int row = blockIdx.x;
    int b = row >> 11;
    int t = threadIdx.x;
    int tx = t & 31, g = t >> 5;
    int nnz = g_nnz[row]; if (nnz > CAP) nnz = CAP;
    const float4* Sb = reinterpret_cast<const float4*>(out + OUT_S) + (size_t)(b << 11) * 32;
    const unsigned short* nb = g_nbr + (size_t)row * CAP;

    __shared__ unsigned short sidx[CAP];
    for (int i = t; i < nnz; i += 128) sidx[i] = nb[i];
    __syncthreads();

    float4 acc = make_float4(0.f, 0.f, 0.f, 0.f);
    int j = g;
    for (; j + 12 < nnz; j += 16) {
        float4 v0 = Sb[(size_t)sidx[j]      * 32 + tx];
        float4 v1 = Sb[(size_t)sidx[j + 4]  * 32 + tx];
        float4 v2 = Sb[(size_t)sidx[j + 8]  * 32 + tx];
        float4 v3 = Sb[(size_t)sidx[j + 12] * 32 + tx];
        acc.x += (v0.x + v1.x) + (v2.x + v3.x);
        acc.y += (v0.y + v1.y) + (v2.y + v3.y);
        acc.z += (v0.z + v1.z) + (v2.z + v3.z);
        acc.w += (v0.w + v1.w) + (v2.w + v3.w);
    }
    for (; j < nnz; j += 4) {
        float4 v = Sb[(size_t)sidx[j] * 32 + tx];
        acc.x += v.x; acc.y += v.y; acc.z += v.z; acc.w += v.w;
    }

    __shared__ float4 sred[4][32];
    sred[g][tx] = acc;
    __syncthreads();
    if (t < 32) {
        float4 a1 = sred[1][tx], a2 = sred[2][tx], a3 = sred[3][tx];
        acc.x = (acc.x + a1.x) + (a2.x + a3.x);
        acc.y = (acc.y + a1.y) + (a2.y + a3.y);
        acc.z = (acc.z + a1.z) + (a2.z + a3.z);
        acc.w = (acc.w + a1.w) + (a2.w + a3.w);
        g_T4[(size_t)row * 32 + tx] = acc;
    }
}

// =====================================================================
// K5: split-K outer-product GEMMs: for p in {0,1,2}: S^T @ {Z, T, S}
// =====================================================================
__global__ void k5_outer(const float* __restrict__ out) {
    int ch = blockIdx.x, b = blockIdx.y, p = blockIdx.z;
    const float* Sb = out + OUT_S + (size_t)b * 262144;
    const float* L = Sb;
    const float* R = (p == 0) ? (reinterpret_cast<const float*>(g_Z4) + (size_t)b * 262144)
                   : (p == 1) ? (reinterpret_cast<const float*>(g_T4) + (size_t)b * 262144)
                   : Sb;
    int t = threadIdx.x;
    int tx = t & 15, ty = t >> 4;
    float acc[8][8];
    #pragma unroll
    for (int i = 0; i < 8; i++)
        #pragma unroll
        for (int j = 0; j < 8; j++) acc[i][j] = 0.f;

    __shared__ float shL[8][128], shR[8][128];
    int n0 = ch * 128;
    for (int nn = 0; nn < 128; nn += 8) {
        __syncthreads();
        #pragma unroll
        for (int r = 0; r < 4; r++) {
            int li = t + (r << 8);
            int rr = li >> 7, cc = li & 127;
            shL[rr][cc] = L[(size_t)(n0 + nn + rr) * 128 + cc];
            shR[rr][cc] = R[(size_t)(n0 + nn + rr) * 128 + cc];
        }
        __syncthreads();
        #pragma unroll
        for (int q = 0; q < 8; q++) {
            float lv[8], rv[8];
            #pragma unroll
            for (int i = 0; i < 8; i++) lv[i] = shL[q][ty * 8 + i];
            #pragma unroll
            for (int j = 0; j < 8; j++) rv[j] = shR[q][tx * 8 + j];
            #pragma unroll
            for (int i = 0; i < 8; i++)
                #pragma unroll
                for (int j = 0; j < 8; j++) acc[i][j] += lv[i] * rv[j];
        }
    }
    float* dst = g_part + (size_t)((p * 8 + b) * 16 + ch) * 16384;
    #pragma unroll
    for (int i = 0; i < 8; i++)
        #pragma unroll
        for (int j = 0; j < 8; j++)
            dst[(ty * 8 + i) * 128 + tx * 8 + j] = acc[i][j];
}

// =====================================================================
// K5b: reduce split-K partials -> X_pooled, A_pooled (out), G (scratch)
// =====================================================================
__global__ void k5b_reduce(float* __restrict__ out) {
    int idx = blockIdx.x * blockDim.x + threadIdx.x;
    if (idx >= 3 * 8 * 16384) return;
    int p = idx / 131072;
    int rem = idx - p * 131072;
    int b = rem >> 14;
    int kc = rem & 16383;
    const float* src = g_part + (size_t)((p * 8 + b) * 16) * 16384 + kc;
    float s = 0.f;
    #pragma unroll
    for (int ch = 0; ch < 16; ch++) s += src[(size_t)ch * 16384];
    if (p == 0)      out[(size_t)b * 16384 + kc] = s;
    else if (p == 1) out[OUT_AP + (size_t)b * 16384 + kc] = s;
    else             g_G[b * 16384 + kc] = s;
}

// =====================================================================
// K6: finalize losses.
// LP_b^2 = sumA_b - 2*trace(A_pooled_b) + ||G_b||_F^2  (A binary => sum(A^2)=sum(A))
// =====================================================================
__global__ void k6_final(float* __restrict__ out) {
    int t = threadIdx.x;                       // 256
    __shared__ float red[256];

    float lo = 0.f;
    for (int i = t; i < ROWS; i += 256) lo += g_entrRow[i];
    red[t] = lo; __syncthreads();
    for (int s2 = 128; s2 > 0; s2 >>= 1) {
        if (t < s2) red[t] += red[t + s2];
        __syncthreads();
    }
    float entr = red[0] / (float)ROWS;
    __syncthreads();

    float lpsum = 0.f;
    for (int b = 0; b < 8; b++) {
        float la = 0.f;
        for (int i = t; i < NN; i += 256) la += (float)g_nnz[b * NN + i];
        red[t] = la; __syncthreads();
        for (int s2 = 128; s2 > 0; s2 >>= 1) { if (t < s2) red[t] += red[t + s2]; __syncthreads(); }
        float sumA = red[0]; __syncthreads();

        float ltr = (t < 128) ? out[OUT_AP + (size_t)b * 16384 + t * 129] : 0.f;
        red[t] = ltr; __syncthreads();
        for (int s2 = 128; s2 > 0; s2 >>= 1) { if (t < s2) red[t] += red[t + s2]; __syncthreads(); }
        float tr = red[0]; __syncthreads();

        float lg = 0.f;
        for (int i = t; i < 16384; i += 256) { float v = g_G[b * 16384 + i]; lg += v * v; }
        red[t] = lg; __syncthreads();
        for (int s2 = 128; s2 > 0; s2 >>= 1) { if (t < s2) red[t] += red[t + s2]; __syncthreads(); }
        float gg = red[0]; __syncthreads();

        lpsum += sqrtf(fmaxf(sumA - 2.f * tr + gg, 0.f));
    }
    if (t == 0) {
        out[OUT_LP] = lpsum / 8.0f;
        out[OUT_ENT] = entr;
    }
}

// =====================================================================
extern "C" void kernel_launch(void* const* d_in, const int* in_sizes, int n_in,
                              void* d_out, int out_size) {
    const float* X  = (const float*)d_in[0];
    const float* A  = (const float*)d_in[1];
    const float* We = (const float*)d_in[2];
    const float* Wp = (const float*)d_in[3];
    float* out = (float*)d_out;

    k1_scan<<<ROWS, 256>>>(A);
    k2_xw<<<ROWS / 32, 256>>>(X, We, Wp);
    k3_prop<<<ROWS, 256>>>(out);
    k4_AS<<<ROWS, 128>>>(out);
    dim3 g5(16, 8, 3);
    k5_outer<<<g5, 256>>>(out);
    k5b_reduce<<<(3 * 8 * 16384 + 255) / 256, 256>>>(out);
    k6_final<<<1, 256>>>(out);
}

// round 3
// speedup vs baseline: 1.5511x; 1.1336x over previous
#include <cuda_runtime.h>

// DiffPool: B=8, N=2048, F=C=K=128.
// out layout (float32): X_pooled[8,128,128] | A_pooled[8,128,128] | S[8,2048,128] | LP_loss | entr_loss
//
// Algebra: fltr = D^-1/2 (A+I) D^-1/2 is symmetric =>
//   X_pooled = S^T (fltr Xe) = (fltr S)^T Xe = U^T Xe,  U = d*(A@(d*S)) + d^2*S
// so the embedding columns are never propagated through A; U shares its gather with T = A@S.

#define BB 8
#define NN 2048
#define ROWS (BB*NN)          // 16384
#define CAP 512               // neighbor-list capacity (mean nnz ~200, max ~260)
#define OUT_AP 131072
#define OUT_S  262144
#define OUT_LP 2359296
#define OUT_ENT 2359297

// ---- scratch (static __device__: no runtime allocation) ----
__device__ float4 g_Yp4[(size_t)ROWS*32];            // d-scaled X@W_pool (128 f32/row)
__device__ float4 g_Xe4[(size_t)ROWS*32];            // raw X@W_emb
__device__ float4 g_T4[(size_t)ROWS*32];             // T = A @ S
__device__ float4 g_U4[(size_t)ROWS*32];             // U = fltr @ S
__device__ float g_d[ROWS];
__device__ int   g_nnz[ROWS];
__device__ unsigned short g_nbr[(size_t)ROWS*CAP];
__device__ float g_entrRow[ROWS];
__device__ float g_part[(size_t)3*8*16*16384];       // split-K partials
__device__ float g_G[8*128*128];                     // G = S^T S

// =====================================================================
// K1: per-row scan of A (float4 loads): nnz, neighbor list, d = rsqrt(sum+1)
// =====================================================================
__global__ void k1_scan(const float* __restrict__ A) {
    int row = blockIdx.x;
    const float4* ar = reinterpret_cast<const float4*>(A + (size_t)row * NN);
    int t = threadIdx.x;                     // 256 threads
    unsigned short loc[8];
    int cnt = 0;
    #pragma unroll
    for (int i = 0; i < 2; i++) {
        int cg = t + (i << 8);
        float4 v = ar[cg];
        int c0 = cg << 2;
        if (v.x != 0.0f) loc[cnt++] = (unsigned short)(c0);
        if (v.y != 0.0f) loc[cnt++] = (unsigned short)(c0 + 1);
        if (v.z != 0.0f) loc[cnt++] = (unsigned short)(c0 + 2);
        if (v.w != 0.0f) loc[cnt++] = (unsigned short)(c0 + 3);
    }
    int lane = t & 31, w = t >> 5;
    int incl = cnt;
    #pragma unroll
    for (int o = 1; o < 32; o <<= 1) {
        int v = __shfl_up_sync(0xffffffffu, incl, o);
        if (lane >= o) incl += v;
    }
    __shared__ int wtot[8], woff[8];
    if (lane == 31) wtot[w] = incl;
    __syncthreads();
    if (t == 0) {
        int s = 0;
        for (int i = 0; i < 8; i++) { woff[i] = s; s += wtot[i]; }
        g_nnz[row] = s;
        g_d[row] = rsqrtf((float)s + 1.0f);
    }
    __syncthreads();
    int off = woff[w] + (incl - cnt);
    unsigned short* dst = g_nbr + (size_t)row * CAP;
    for (int i = 0; i < cnt; i++) {
        int o = off + i;
        if (o < CAP) dst[o] = loc[i];
    }
}

// =====================================================================
// K2: Xe = X@W_emb (raw); Yp = d * (X@W_pool)
// =====================================================================
__global__ void k2_xw(const float* __restrict__ X, const float* __restrict__ We,
                      const float* __restrict__ Wp) {
    __shared__ float shW[32][256];
    __shared__ float shX[32][32];
    int t = threadIdx.x;
    int tx = t & 31, ty = t >> 5;
    int row0 = blockIdx.x * 32;
    float acc[4][8];
    #pragma unroll
    for (int i = 0; i < 4; i++)
        #pragma unroll
        for (int j = 0; j < 8; j++) acc[i][j] = 0.f;

    for (int kb = 0; kb < 4; kb++) {
        __syncthreads();
        #pragma unroll
        for (int r = 0; r < 32; r++) {
            int k = kb * 32 + r;
            shW[r][t] = (t < 128) ? We[k * 128 + t] : Wp[k * 128 + (t - 128)];
        }
        #pragma unroll
        for (int r = 0; r < 4; r++) {
            int li = t + (r << 8);
            int rr = li >> 5, kk = li & 31;
            shX[rr][kk] = X[(size_t)(row0 + rr) * 128 + kb * 32 + kk];
        }
        __syncthreads();
        #pragma unroll
        for (int kk = 0; kk < 32; kk++) {
            float x0 = shX[ty][kk], x1 = shX[ty + 8][kk];
            float x2 = shX[ty + 16][kk], x3 = shX[ty + 24][kk];
            float wv[8];
            #pragma unroll
            for (int j = 0; j < 8; j++) wv[j] = shW[kk][tx * 8 + j];
            #pragma unroll
            for (int j = 0; j < 8; j++) {
                acc[0][j] += x0 * wv[j];
                acc[1][j] += x1 * wv[j];
                acc[2][j] += x2 * wv[j];
                acc[3][j] += x3 * wv[j];
            }
        }
    }
    #pragma unroll
    for (int r = 0; r < 4; r++) {
        int row = row0 + ty + r * 8;
        float dv = g_d[row];
        #pragma unroll
        for (int jj = 0; jj < 2; jj++) {
            float4 v;
            if (tx < 16) {          // emb cols 0..127: raw
                v.x = acc[r][jj * 4 + 0]; v.y = acc[r][jj * 4 + 1];
                v.z = acc[r][jj * 4 + 2]; v.w = acc[r][jj * 4 + 3];
                g_Xe4[(size_t)row * 32 + tx * 2 + jj] = v;
            } else {                // pool cols: scaled by d
                v.x = dv * acc[r][jj * 4 + 0]; v.y = dv * acc[r][jj * 4 + 1];
                v.z = dv * acc[r][jj * 4 + 2]; v.w = dv * acc[r][jj * 4 + 3];
                g_Yp4[(size_t)row * 32 + (tx - 16) * 2 + jj] = v;
            }
        }
    }
}

// =====================================================================
// K3: gather Yp (128 cols) -> logits -> softmax S + entropy.
// block 128: tx = float4 group (0..31), g = neighbor subset (0..3)
// =====================================================================
__global__ void k3_prop(float* __restrict__ out) {
    int row = blockIdx.x;
    int b = row >> 11;
    int t = threadIdx.x;
    int tx = t & 31, g = t >> 5;
    float d = g_d[row];
    int nnz = g_nnz[row]; if (nnz > CAP) nnz = CAP;
    const float4* Yb = g_Yp4 + (size_t)(b << 11) * 32;
    const unsigned short* nb = g_nbr + (size_t)row * CAP;

    __shared__ unsigned short sidx[CAP];
    for (int i = t; i < nnz; i += 128) sidx[i] = nb[i];
    __syncthreads();

    float4 acc = make_float4(0.f, 0.f, 0.f, 0.f);
    if (g == 0) acc = g_Yp4[(size_t)row * 32 + tx];     // identity (+I) term
    int j = g;
    for (; j + 12 < nnz; j += 16) {
        float4 v0 = Yb[(size_t)sidx[j]      * 32 + tx];
        float4 v1 = Yb[(size_t)sidx[j + 4]  * 32 + tx];
        float4 v2 = Yb[(size_t)sidx[j + 8]  * 32 + tx];
        float4 v3 = Yb[(size_t)sidx[j + 12] * 32 + tx];
        acc.x += (v0.x + v1.x) + (v2.x + v3.x);
        acc.y += (v0.y + v1.y) + (v2.y + v3.y);
        acc.z += (v0.z + v1.z) + (v2.z + v3.z);
        acc.w += (v0.w + v1.w) + (v2.w + v3.w);
    }
    for (; j < nnz; j += 4) {
        float4 v = Yb[(size_t)sidx[j] * 32 + tx];
        acc.x += v.x; acc.y += v.y; acc.z += v.z; acc.w += v.w;
    }

    __shared__ float4 sred[4][32];
    sred[g][tx] = acc;
    __syncthreads();
    if (t < 32) {
        float4 a1 = sred[1][tx], a2 = sred[2][tx], a3 = sred[3][tx];
        float4 lg;
        lg.x = d * ((acc.x + a1.x) + (a2.x + a3.x));
        lg.y = d * ((acc.y + a1.y) + (a2.y + a3.y));
        lg.z = d * ((acc.z + a1.z) + (a2.z + a3.z));
        lg.w = d * ((acc.w + a1.w) + (a2.w + a3.w));
        float m = fmaxf(fmaxf(lg.x, lg.y), fmaxf(lg.z, lg.w));
        #pragma unroll
        for (int o = 16; o > 0; o >>= 1) m = fmaxf(m, __shfl_xor_sync(0xffffffffu, m, o));
        float ex = expf(lg.x - m), ey = expf(lg.y - m);
        float ez = expf(lg.z - m), ew = expf(lg.w - m);
        float ssum = (ex + ey) + (ez + ew);
        #pragma unroll
        for (int o = 16; o > 0; o >>= 1) ssum += __shfl_xor_sync(0xffffffffu, ssum, o);
        float inv = 1.f / ssum;
        float4 s4; s4.x = ex * inv; s4.y = ey * inv; s4.z = ez * inv; s4.w = ew * inv;
        reinterpret_cast<float4*>(out + OUT_S)[(size_t)row * 32 + tx] = s4;
        float ent = -(s4.x * logf(s4.x + 1e-7f) + s4.y * logf(s4.y + 1e-7f)
                    + s4.z * logf(s4.z + 1e-7f) + s4.w * logf(s4.w + 1e-7f));
        #pragma unroll
        for (int o = 16; o > 0; o >>= 1) ent += __shfl_xor_sync(0xffffffffu, ent, o);
        if (tx == 0) g_entrRow[row] = ent;
    }
}

// =====================================================================
// K4: fused dual gather over S: T = A@S, U = d*(A@(d*S)) + d^2*S.
// Same loads as a single gather; two FMA targets.
// =====================================================================
__global__ void k4_AS(const float* __restrict__ out) {
    int row = blockIdx.x;
    int b = row >> 11;
    int t = threadIdx.x;
    int tx = t & 31, g = t >> 5;
    int nnz = g_nnz[row]; if (nnz > CAP) nnz = CAP;
    const float4* Sb = reinterpret_cast<const float4*>(out + OUT_S) + (size_t)(b << 11) * 32;
    const unsigned short* nb = g_nbr + (size_t)row * CAP;
    const float* db = g_d + (b << 11);

    __shared__ unsigned short sidx[CAP];
    __shared__ float sdv[CAP];
    for (int i = t; i < nnz; i += 128) {
        int m = nb[i];
        sidx[i] = (unsigned short)m;
        sdv[i] = db[m];
    }
    __syncthreads();

    float4 aP = make_float4(0.f, 0.f, 0.f, 0.f);
    float4 aS = make_float4(0.f, 0.f, 0.f, 0.f);
    int j = g;
    for (; j + 12 < nnz; j += 16) {
        float4 v0 = Sb[(size_t)sidx[j]      * 32 + tx];
        float4 v1 = Sb[(size_t)sidx[j + 4]  * 32 + tx];
        float4 v2 = Sb[(size_t)sidx[j + 8]  * 32 + tx];
        float4 v3 = Sb[(size_t)sidx[j + 12] * 32 + tx];
        float d0 = sdv[j], d1 = sdv[j + 4], d2 = sdv[j + 8], d3 = sdv[j + 12];
        aP.x += (v0.x + v1.x) + (v2.x + v3.x);
        aP.y += (v0.y + v1.y) + (v2.y + v3.y);
        aP.z += (v0.z + v1.z) + (v2.z + v3.z);
        aP.w += (v0.w + v1.w) + (v2.w + v3.w);
        aS.x += (d0 * v0.x + d1 * v1.x) + (d2 * v2.x + d3 * v3.x);
        aS.y += (d0 * v0.y + d1 * v1.y) + (d2 * v2.y + d3 * v3.y);
        aS.z += (d0 * v0.z + d1 * v1.z) + (d2 * v2.z + d3 * v3.z);
        aS.w += (d0 * v0.w + d1 * v1.w) + (d2 * v2.w + d3 * v3.w);
    }
    for (; j < nnz; j += 4) {
        float4 v = Sb[(size_t)sidx[j] * 32 + tx];
        float dj = sdv[j];
        aP.x += v.x; aP.y += v.y; aP.z += v.z; aP.w += v.w;
        aS.x += dj * v.x; aS.y += dj * v.y; aS.z += dj * v.z; aS.w += dj * v.w;
    }

    __shared__ float4 srP[4][32], srS[4][32];
    srP[g][tx] = aP; srS[g][tx] = aS;
    __syncthreads();
    if (t < 32) {
        float4 p1 = srP[1][tx], p2 = srP[2][tx], p3 = srP[3][tx];
        float4 s1 = srS[1][tx], s2 = srS[2][tx], s3 = srS[3][tx];
        aP.x = (aP.x + p1.x) + (p2.x + p3.x);
        aP.y = (aP.y + p1.y) + (p2.y + p3.y);
        aP.z = (aP.z + p1.z) + (p2.z + p3.z);
        aP.w = (aP.w + p1.w) + (p2.w + p3.w);
        aS.x = (aS.x + s1.x) + (s2.x + s3.x);
        aS.y = (aS.y + s1.y) + (s2.y + s3.y);
        aS.z = (aS.z + s1.z) + (s2.z + s3.z);
        aS.w = (aS.w + s1.w) + (s2.w + s3.w);
        g_T4[(size_t)row * 32 + tx] = aP;
        float dn = g_d[row];
        float dn2 = dn * dn;
        float4 s0 = Sb[((size_t)(row & (NN - 1))) * 32 + tx];
        float4 u;
        u.x = dn * aS.x + dn2 * s0.x;
        u.y = dn * aS.y + dn2 * s0.y;
        u.z = dn * aS.z + dn2 * s0.z;
        u.w = dn * aS.w + dn2 * s0.w;
        g_U4[(size_t)row * 32 + tx] = u;
    }
}

// =====================================================================
// K5: split-K outer-product GEMMs: p0: U^T Xe, p1: S^T T, p2: S^T S
// =====================================================================
__global__ void k5_outer(const float* __restrict__ out) {
    int ch = blockIdx.x, b = blockIdx.y, p = blockIdx.z;
    const float* Sb = out + OUT_S + (size_t)b * 262144;
    const float* L = (p == 0) ? (reinterpret_cast<const float*>(g_U4) + (size_t)b * 262144) : Sb;
    const float* R = (p == 0) ? (reinterpret_cast<const float*>(g_Xe4) + (size_t)b * 262144)
                   : (p == 1) ? (reinterpret_cast<const float*>(g_T4) + (size_t)b * 262144)
                   : Sb;
    int t = threadIdx.x;
    int tx = t & 15, ty = t >> 4;
    float acc[8][8];
    #pragma unroll
    for (int i = 0; i < 8; i++)
        #pragma unroll
        for (int j = 0; j < 8; j++) acc[i][j] = 0.f;

    __shared__ float shL[8][128], shR[8][128];
    int n0 = ch * 128;
    for (int nn = 0; nn < 128; nn += 8) {
        __syncthreads();
        #pragma unroll
        for (int r = 0; r < 4; r++) {
            int li = t + (r << 8);
            int rr = li >> 7, cc = li & 127;
            shL[rr][cc] = L[(size_t)(n0 + nn + rr) * 128 + cc];
            shR[rr][cc] = R[(size_t)(n0 + nn + rr) * 128 + cc];
        }
        __syncthreads();
        #pragma unroll
        for (int q = 0; q < 8; q++) {
            float lv[8], rv[8];
            #pragma unroll
            for (int i = 0; i < 8; i++) lv[i] = shL[q][ty * 8 + i];
            #pragma unroll
            for (int j = 0; j < 8; j++) rv[j] = shR[q][tx * 8 + j];
            #pragma unroll
            for (int i = 0; i < 8; i++)
                #pragma unroll
                for (int j = 0; j < 8; j++) acc[i][j] += lv[i] * rv[j];
        }
    }
    float* dst = g_part + (size_t)((p * 8 + b) * 16 + ch) * 16384;
    #pragma unroll
    for (int i = 0; i < 8; i++)
        #pragma unroll
        for (int j = 0; j < 8; j++)
            dst[(ty * 8 + i) * 128 + tx * 8 + j] = acc[i][j];
}

// =====================================================================
// K5b: reduce split-K partials -> X_pooled, A_pooled (out), G (scratch)
// =====================================================================
__global__ void k5b_reduce(float* __restrict__ out) {
    int idx = blockIdx.x * blockDim.x + threadIdx.x;
    if (idx >= 3 * 8 * 16384) return;
    int p = idx / 131072;
    int rem = idx - p * 131072;
    int b = rem >> 14;
    int kc = rem & 16383;
    const float* src = g_part + (size_t)((p * 8 + b) * 16) * 16384 + kc;
    float s = 0.f;
    #pragma unroll
    for (int ch = 0; ch < 16; ch++) s += src[(size_t)ch * 16384];
    if (p == 0)      out[(size_t)b * 16384 + kc] = s;
    else if (p == 1) out[OUT_AP + (size_t)b * 16384 + kc] = s;
    else             g_G[b * 16384 + kc] = s;
}

// =====================================================================
// K6: finalize losses. LP_b^2 = sumA_b - 2*tr(A_pooled_b) + ||G_b||_F^2
// =====================================================================
__global__ void k6_final(float* __restrict__ out) {
    int t = threadIdx.x;                       // 256
    __shared__ float red[256];

    float lo = 0.f;
    for (int i = t; i < ROWS; i += 256) lo += g_entrRow[i];
    red[t] = lo; __syncthreads();
    for (int s2 = 128; s2 > 0; s2 >>= 1) {
        if (t < s2) red[t] += red[t + s2];
        __syncthreads();
    }
    float entr = red[0] / (float)ROWS;
    __syncthreads();

    float lpsum = 0.f;
    for (int b = 0; b < 8; b++) {
        float la = 0.f;
        for (int i = t; i < NN; i += 256) la += (float)g_nnz[b * NN + i];
        red[t] = la; __syncthreads();
        for (int s2 = 128; s2 > 0; s2 >>= 1) { if (t < s2) red[t] += red[t + s2]; __syncthreads(); }
        float sumA = red[0]; __syncthreads();

        float ltr = (t < 128) ? out[OUT_AP + (size_t)b * 16384 + t * 129] : 0.f;
        red[t] = ltr; __syncthreads();
        for (int s2 = 128; s2 > 0; s2 >>= 1) { if (t < s2) red[t] += red[t + s2]; __syncthreads(); }
        float tr = red[0]; __syncthreads();

        float lg = 0.f;
        for (int i = t; i < 16384; i += 256) { float v = g_G[b * 16384 + i]; lg += v * v; }
        red[t] = lg; __syncthreads();
        for (int s2 = 128; s2 > 0; s2 >>= 1) { if (t < s2) red[t] += red[t + s2]; __syncthreads(); }
        float gg = red[0]; __syncthreads();

        lpsum += sqrtf(fmaxf(sumA - 2.f * tr + gg, 0.f));
    }
    if (t == 0) {
        out[OUT_LP] = lpsum / 8.0f;
        out[OUT_ENT] = entr;
    }
}

// =====================================================================
extern "C" void kernel_launch(void* const* d_in, const int* in_sizes, int n_in,
                              void* d_out, int out_size) {
    const float* X  = (const float*)d_in[0];
    const float* A  = (const float*)d_in[1];
    const float* We = (const float*)d_in[2];
    const float* Wp = (const float*)d_in[3];
    float* out = (float*)d_out;

    k1_scan<<<ROWS, 256>>>(A);
    k2_xw<<<ROWS / 32, 256>>>(X, We, Wp);
    k3_prop<<<ROWS, 128>>>(out);
    k4_AS<<<ROWS, 128>>>(out);
    dim3 g5(16, 8, 3);
    k5_outer<<<g5, 256>>>(out);
    k5b_reduce<<<(3 * 8 * 16384 + 255) / 256, 256>>>(out);
    k6_final<<<1, 256>>>(out);
}